// round 15
// baseline (speedup 1.0000x reference)
#include <cuda_runtime.h>
#include <cuda_bf16.h>
#include <math.h>
#include <stdint.h>

#define BB     32
#define LL     4096
#define DIN    150
#define DST    75
#define HID    75
#define HIDP   80
#define TILE_L 128
#define NCHUNK (LL / TILE_L)     // 32
#define WORKS  (BB * NCHUNK)     // 1024
#define GRIDC  148
#define NTH    640               // 16 GEMM warps + 4 aux warps
#define NGEMM  512
#define NAUX   128
#define TFLOATS (TILE_L * DIN)   // 19200
#define CHUNK16 (TFLOATS * 4 / 16)
#define WKS    168               // W row stride in bf16 (21*16B, conflict-free LDSM)
#define WROWB  (WKS * 2)
#define WFLOATS (HIDP * WKS / 2) // 6720 floats per matrix

// smem float offsets
#define OFF_XS0 0
#define OFF_XS1 19200
#define OFF_WH  38400
#define OFF_WL  (OFF_WH + WFLOATS)
#define OFF_SPB (OFF_WL + WFLOATS)
#define OFF_W1  (OFF_SPB + BB * HIDP)
#define OFF_ES  (OFF_W1 + HIDP)          // es[2][128]
#define OFF_PS  (OFF_ES + 2 * TILE_L)
#define OFF_SC  (OFF_PS + 8)             // scomb[128]
#define SMEM_FLOATS (OFF_SC + TILE_L)

__device__ float g_part[BB][NCHUNK][160];
__device__ float g_psum[BB][NCHUNK];
__device__ int   g_done_b[BB];

__device__ __forceinline__ float tanh_approx(float x) {
    float t; asm("tanh.approx.f32 %0, %1;" : "=f"(t) : "f"(x)); return t;
}
__device__ __forceinline__ void cp16(uint32_t saddr, const void* gptr) {
    asm volatile("cp.async.cg.shared.global [%0], [%1], 16;" :: "r"(saddr), "l"(gptr));
}
__device__ __forceinline__ void cp_commit() { asm volatile("cp.async.commit_group;"); }
__device__ __forceinline__ void cp_wait0()  { asm volatile("cp.async.wait_group 0;"); }
__device__ __forceinline__ uint32_t smem_u32(const void* p) {
    uint32_t a;
    asm("{ .reg .u64 t; cvta.to.shared.u64 t, %1; cvt.u32.u64 %0, t; }" : "=r"(a) : "l"(p));
    return a;
}
__device__ __forceinline__ uint32_t bfpack(float2 f) {
    uint32_t r;
    asm("cvt.rn.bf16x2.f32 %0, %1, %2;" : "=r"(r) : "f"(f.y), "f"(f.x));
    return r;
}
__device__ __forceinline__ uint32_t bfres(float2 f, uint32_t h) {
    float hx = __uint_as_float(h << 16);
    float hy = __uint_as_float(h & 0xffff0000u);
    float2 r; r.x = f.x - hx; r.y = f.y - hy;
    return bfpack(r);
}
#define AUX_BAR()  asm volatile("bar.sync 1, %0;" :: "n"(NAUX)  : "memory")
#define GEMM_BAR() asm volatile("bar.sync 2, %0;" :: "n"(NGEMM) : "memory")

#define LDSM_X4(r0, r1, r2, r3, addr) \
    asm volatile("ldmatrix.sync.aligned.m8n8.x4.shared.b16 {%0,%1,%2,%3}, [%4];" \
                 : "=r"(r0), "=r"(r1), "=r"(r2), "=r"(r3) : "r"(addr))

#define MMA_BF16(d, a0, a1, a2, a3, b0, b1) \
    asm volatile("mma.sync.aligned.m16n8k16.row.col.f32.bf16.bf16.f32 " \
                 "{%0,%1,%2,%3}, {%4,%5,%6,%7}, {%8,%9}, {%0,%1,%2,%3};" \
                 : "+f"((d)[0]), "+f"((d)[1]), "+f"((d)[2]), "+f"((d)[3]) \
                 : "r"(a0), "r"(a1), "r"(a2), "r"(a3), "r"(b0), "r"(b1))

// ---------------------------------------------------------------------------
// Persistent warp-specialized fused kernel, n-split GEMM.
// Warps 0-15: bf16 3x mma.sync GEMM, 16 rows x 40 cols each (8 row-blocks x
// 2 col-halves); epilogue combines col-halves via smem + named barrier.
// Warps 16-19 (aux): weighted partials + psum + finish for tile wi-1, then
// cp.async staging of tile wi+1.
// ---------------------------------------------------------------------------
__global__ __launch_bounds__(NTH, 1)
void k_fused(const float* __restrict__ inputs,
             const float* __restrict__ state,
             const int*   __restrict__ cmask,
             const float* __restrict__ W0,
             const float* __restrict__ b0,
             const float* __restrict__ W1,
             const float* __restrict__ b1,
             float* __restrict__ res,
             float* __restrict__ s1_out) {
    extern __shared__ float sm[];
    float* xsbuf[2] = { sm + OFF_XS0, sm + OFF_XS1 };
    float* whf     = sm + OFF_WH;
    float* wlf     = sm + OFF_WL;
    float* spb_all = sm + OFF_SPB;
    float* w1s     = sm + OFF_W1;
    float* esb     = sm + OFF_ES;       // [2][TILE_L]
    float* psred   = sm + OFF_PS;
    float* scomb   = sm + OFF_SC;       // [TILE_L]
    __shared__ int s_flag;

    const int tid   = threadIdx.x;
    const int cta   = blockIdx.x;
    const int nw    = (WORKS - cta + GRIDC - 1) / GRIDC;
    const bool is_aux = (tid >= NGEMM);
    const int a_tid = tid - NGEMM;      // 0..127 for aux
    const int lane  = tid & 31;
    const int g     = lane >> 2;
    const int tq    = lane & 3;
    const int wid   = tid >> 5;
    const int rb    = wid & 7;          // row block (GEMM warps)
    const int ch    = (wid >> 3) & 1;   // col half
    const int R0    = rb << 4;

    // --- aux: issue prefetch of tile 0 immediately ---
    if (is_aux) {
        int b = cta >> 5, chunk = cta & 31;
        const char* gb = (const char*)(inputs + ((size_t)b * LL + chunk * TILE_L) * DIN);
        uint32_t sb = smem_u32(xsbuf[0]);
        for (int c = a_tid; c < CHUNK16; c += NAUX) cp16(sb + c * 16, gb + (size_t)c * 16);
        cp_commit();
    }

    // --- stage W hi/lo bf16 (once): zero pads, then fill ---
    for (int idx = tid; idx < 2 * WFLOATS; idx += NTH) whf[idx] = 0.0f;
    __syncthreads();
    for (int idx = tid; idx < 150 * HIDP; idx += NTH) {
        int k = idx / HIDP, j = idx - (idx / HIDP) * HIDP;
        float v = (j < HID) ? W0[(DST + k) * HID + j] : 0.0f;
        __nv_bfloat16 h = __float2bfloat16(v);
        float l = v - __bfloat162float(h);
        ((__nv_bfloat16*)whf)[j * WKS + k] = h;
        ((__nv_bfloat16*)wlf)[j * WKS + k] = __float2bfloat16(l);
    }
    for (int idx = tid; idx < BB * HIDP; idx += NTH) {
        int b = idx / HIDP, j = idx - (idx / HIDP) * HIDP;
        float acc = 0.0f;
        if (j < HID) {
            acc = b0[j];
            const float* st = state + b * DST;
#pragma unroll 15
            for (int k = 0; k < DST; ++k) acc = fmaf(st[k], W0[k * HID + j], acc);
        }
        spb_all[idx] = acc;
    }
    if (tid < HIDP) w1s[tid] = (tid < HID) ? W1[tid] : 0.0f;

    const float b1v = b1[0];
    const uint32_t whb4 = smem_u32(whf) + (lane & 7) * WROWB + (lane >> 3) * 16
                        + ch * 5 * 2688;                 // col-half offset
    const uint32_t wlb4 = whb4 + WFLOATS * 4;

    // ---------------- persistent work loop ----------------
    for (int wi = 0; wi < nw; ++wi) {
        const int w     = cta + wi * GRIDC;
        const int b     = w >> 5;
        const int chunk = w & 31;
        const int l0    = chunk * TILE_L;
        const float* xsb = xsbuf[wi & 1];
        float* es = esb + (wi & 1) * TILE_L;

        if (is_aux) cp_wait0();          // tile wi staged
        __syncthreads();                 // tile wi + es/scomb reuse visible

        if (!is_aux) {
            // ================= GEMM warps: tile wi =================
            float acc[5][4];
#pragma unroll
            for (int n = 0; n < 5; ++n)
#pragma unroll
                for (int c = 0; c < 4; ++c) acc[n][c] = 0.0f;

            const float* row0 = xsb + (size_t)(R0 + g) * DIN;
            const float* row8 = row0 + 8 * DIN;

#pragma unroll
            for (int sp = 0; sp < 5; ++sp) {
                const int kpE = sp * 32 + tq * 2;
                const int kpO = kpE + 16;
                float2 e00 = *(const float2*)(row0 + kpE);
                float2 e10 = *(const float2*)(row8 + kpE);
                float2 e01 = *(const float2*)(row0 + kpE + 8);
                float2 e11 = *(const float2*)(row8 + kpE + 8);
                float2 o00, o10, o01, o11;
                if (sp < 4) {
                    o00 = *(const float2*)(row0 + kpO);
                    o10 = *(const float2*)(row8 + kpO);
                    o01 = *(const float2*)(row0 + kpO + 8);
                    o11 = *(const float2*)(row8 + kpO + 8);
                } else {
                    o01 = make_float2(0.f, 0.f); o11 = o01;
                    if (tq < 3) {
                        o00 = *(const float2*)(row0 + kpO);
                        o10 = *(const float2*)(row8 + kpO);
                    } else { o00 = o01; o10 = o01; }
                }
                uint32_t ahE0 = bfpack(e00), ahE1 = bfpack(e10);
                uint32_t ahE2 = bfpack(e01), ahE3 = bfpack(e11);
                uint32_t alE0 = bfres(e00, ahE0), alE1 = bfres(e10, ahE1);
                uint32_t alE2 = bfres(e01, ahE2), alE3 = bfres(e11, ahE3);
                uint32_t ahO0 = bfpack(o00), ahO1 = bfpack(o10);
                uint32_t ahO2 = bfpack(o01), ahO3 = bfpack(o11);
                uint32_t alO0 = bfres(o00, ahO0), alO1 = bfres(o10, ahO1);
                uint32_t alO2 = bfres(o01, ahO2), alO3 = bfres(o11, ahO3);
#pragma unroll
                for (int n = 0; n < 5; ++n) {
                    uint32_t bh0, bh1, bh2, bh3, bl0, bl1, bl2, bl3;
                    LDSM_X4(bh0, bh1, bh2, bh3, whb4 + n * 2688 + sp * 64);
                    LDSM_X4(bl0, bl1, bl2, bl3, wlb4 + n * 2688 + sp * 64);
                    MMA_BF16(acc[n], ahE0, ahE1, ahE2, ahE3, bh0, bh1);
                    MMA_BF16(acc[n], ahE0, ahE1, ahE2, ahE3, bl0, bl1);
                    MMA_BF16(acc[n], alE0, alE1, alE2, alE3, bh0, bh1);
                    MMA_BF16(acc[n], ahO0, ahO1, ahO2, ahO3, bh2, bh3);
                    MMA_BF16(acc[n], ahO0, ahO1, ahO2, ahO3, bl2, bl3);
                    MMA_BF16(acc[n], alO0, alO1, alO2, alO3, bh2, bh3);
                }
            }

            // epilogue: tanh + dot(W1) over this warp's 40 cols
            const float* spb = spb_all + b * HIDP;
            float sA = 0.0f, sB = 0.0f;
#pragma unroll
            for (int n = 0; n < 5; ++n) {
                int c = (ch * 5 + n) * 8 + tq * 2;
                float wv0 = w1s[c], wv1 = w1s[c + 1];
                float p0 = spb[c],  p1 = spb[c + 1];
                sA = fmaf(tanh_approx(acc[n][0] + p0), wv0, sA);
                sA = fmaf(tanh_approx(acc[n][1] + p1), wv1, sA);
                sB = fmaf(tanh_approx(acc[n][2] + p0), wv0, sB);
                sB = fmaf(tanh_approx(acc[n][3] + p1), wv1, sB);
            }
            sA += __shfl_xor_sync(0xffffffffu, sA, 1);
            sA += __shfl_xor_sync(0xffffffffu, sA, 2);
            sB += __shfl_xor_sync(0xffffffffu, sB, 1);
            sB += __shfl_xor_sync(0xffffffffu, sB, 2);
            // combine col-halves
            if (ch == 1 && tq == 0) {
                scomb[R0 + g] = sA;
                scomb[R0 + g + 8] = sB;
            }
            GEMM_BAR();
            if (ch == 0 && tq == 0) {
                int r = R0 + g;
                size_t idx = (size_t)b * LL + l0 + r;
                float sv = sA + scomb[r] + b1v;
                if (cmask[idx] == 0) sv -= 1e30f;
                s1_out[idx] = sv;
                es[r] = __expf(sv);
                int r2 = r + 8;
                size_t idx2 = (size_t)b * LL + l0 + r2;
                float sv2 = sB + scomb[r2] + b1v;
                if (cmask[idx2] == 0) sv2 -= 1e30f;
                s1_out[idx2] = sv2;
                es[r2] = __expf(sv2);
            }
        } else {
            // ================= aux warps =================
            if (wi > 0) {
                const int wp  = cta + (wi - 1) * GRIDC;
                const int bp  = wp >> 5;
                const int chp = wp & 31;
                const float* xp = xsbuf[(wi - 1) & 1];
                const float* ep = esb + ((wi - 1) & 1) * TILE_L;

                for (int f = a_tid; f < DIN; f += NAUX) {
                    const float* xcol = xp + f;
                    float p0 = 0.f, p1 = 0.f, p2 = 0.f, p3 = 0.f;
#pragma unroll 4
                    for (int r = 0; r < TILE_L; r += 4) {
                        p0 = fmaf(ep[r],     xcol[(size_t)r * DIN],       p0);
                        p1 = fmaf(ep[r + 1], xcol[(size_t)(r + 1) * DIN], p1);
                        p2 = fmaf(ep[r + 2], xcol[(size_t)(r + 2) * DIN], p2);
                        p3 = fmaf(ep[r + 3], xcol[(size_t)(r + 3) * DIN], p3);
                    }
                    g_part[bp][chp][f] = (p0 + p1) + (p2 + p3);
                }
                {
                    float v = ep[a_tid];
                    v += __shfl_xor_sync(0xffffffffu, v, 16);
                    v += __shfl_xor_sync(0xffffffffu, v, 8);
                    v += __shfl_xor_sync(0xffffffffu, v, 4);
                    v += __shfl_xor_sync(0xffffffffu, v, 2);
                    v += __shfl_xor_sync(0xffffffffu, v, 1);
                    if ((a_tid & 31) == 0) psred[a_tid >> 5] = v;
                }
                AUX_BAR();
                if (a_tid == 0) {
                    g_psum[bp][chp] = (psred[0] + psred[1]) + (psred[2] + psred[3]);
                    __threadfence();
                    int old = atomicAdd(&g_done_b[bp], 1);
                    s_flag = (old == NCHUNK - 1);
                }
                AUX_BAR();
                if (s_flag) {
                    __threadfence();
                    for (int f = a_tid; f < DIN; f += NAUX) {
                        float tot = 0.0f;
#pragma unroll
                        for (int c = 0; c < NCHUNK; ++c) tot += g_psum[bp][c];
                        float p = 0.0f;
#pragma unroll
                        for (int c = 0; c < NCHUNK; ++c) p += g_part[bp][c][f];
                        res[bp * DIN + f] = p / tot;
                    }
                    if (a_tid == 0) g_done_b[bp] = 0;
                }
                AUX_BAR();
            }
            if (wi + 1 < nw) {
                int w2 = cta + (wi + 1) * GRIDC;
                int b2 = w2 >> 5, ch2 = w2 & 31;
                const char* gb = (const char*)(inputs + ((size_t)b2 * LL + ch2 * TILE_L) * DIN);
                uint32_t sb = smem_u32(xsbuf[(wi + 1) & 1]);
                for (int c = a_tid; c < CHUNK16; c += NAUX)
                    cp16(sb + c * 16, gb + (size_t)c * 16);
                cp_commit();
            }
        }
    }

    // ---------------- tail: partials/finish for last tile ----------------
    __syncthreads();
    if (is_aux) {
        const int wp  = cta + (nw - 1) * GRIDC;
        const int bp  = wp >> 5;
        const int chp = wp & 31;
        const float* xp = xsbuf[(nw - 1) & 1];
        const float* ep = esb + ((nw - 1) & 1) * TILE_L;
        for (int f = a_tid; f < DIN; f += NAUX) {
            const float* xcol = xp + f;
            float p0 = 0.f, p1 = 0.f, p2 = 0.f, p3 = 0.f;
#pragma unroll 4
            for (int r = 0; r < TILE_L; r += 4) {
                p0 = fmaf(ep[r],     xcol[(size_t)r * DIN],       p0);
                p1 = fmaf(ep[r + 1], xcol[(size_t)(r + 1) * DIN], p1);
                p2 = fmaf(ep[r + 2], xcol[(size_t)(r + 2) * DIN], p2);
                p3 = fmaf(ep[r + 3], xcol[(size_t)(r + 3) * DIN], p3);
            }
            g_part[bp][chp][f] = (p0 + p1) + (p2 + p3);
        }
        {
            float v = ep[a_tid];
            v += __shfl_xor_sync(0xffffffffu, v, 16);
            v += __shfl_xor_sync(0xffffffffu, v, 8);
            v += __shfl_xor_sync(0xffffffffu, v, 4);
            v += __shfl_xor_sync(0xffffffffu, v, 2);
            v += __shfl_xor_sync(0xffffffffu, v, 1);
            if ((a_tid & 31) == 0) psred[a_tid >> 5] = v;
        }
        AUX_BAR();
        if (a_tid == 0) {
            g_psum[bp][chp] = (psred[0] + psred[1]) + (psred[2] + psred[3]);
            __threadfence();
            int old = atomicAdd(&g_done_b[bp], 1);
            s_flag = (old == NCHUNK - 1);
        }
        AUX_BAR();
        if (s_flag) {
            __threadfence();
            for (int f = a_tid; f < DIN; f += NAUX) {
                float tot = 0.0f;
#pragma unroll
                for (int c = 0; c < NCHUNK; ++c) tot += g_psum[bp][c];
                float p = 0.0f;
#pragma unroll
                for (int c = 0; c < NCHUNK; ++c) p += g_part[bp][c][f];
                res[bp * DIN + f] = p / tot;
            }
            if (a_tid == 0) g_done_b[bp] = 0;
        }
    }
}

// ---------------------------------------------------------------------------
extern "C" void kernel_launch(void* const* d_in, const int* in_sizes, int n_in,
                              void* d_out, int out_size) {
    const float* inputs = (const float*)d_in[0];
    const float* state  = (const float*)d_in[1];
    const int*   cmask  = (const int*)d_in[2];   // bool transported as int32
    const float* W0     = (const float*)d_in[3];
    const float* b0     = (const float*)d_in[4];
    const float* W1     = (const float*)d_in[5];
    const float* b1     = (const float*)d_in[6];

    float* out = (float*)d_out;
    float* res = out;                 // [B][1][DIN]
    float* s1  = out + BB * DIN;      // [B][L]

    const int smem = SMEM_FLOATS * (int)sizeof(float);
    cudaFuncSetAttribute(k_fused, cudaFuncAttributeMaxDynamicSharedMemorySize, smem);
    k_fused<<<GRIDC, NTH, smem>>>(inputs, state, cmask, W0, b0, W1, b1, res, s1);
}

// round 16
// speedup vs baseline: 1.1041x; 1.1041x over previous
#include <cuda_runtime.h>
#include <cuda_bf16.h>
#include <math.h>
#include <stdint.h>

#define BB     32
#define LL     4096
#define DIN    150
#define DST    75
#define HID    75
#define HIDP   80
#define TILE_L 128
#define NCHUNK (LL / TILE_L)     // 32
#define WORKS  (BB * NCHUNK)     // 1024
#define GRIDC  148
#define NTH    384               // 8 GEMM warps + 4 aux warps
#define NAUX   128
#define TFLOATS (TILE_L * DIN)   // 19200
#define CHUNK16 (TFLOATS * 4 / 16)
#define WKS    168               // W row stride in bf16 (21*16B, conflict-free LDSM)
#define WROWB  (WKS * 2)
#define WFLOATS (HIDP * WKS / 2) // 6720 floats per matrix

// smem float offsets
#define OFF_XS0 0
#define OFF_XS1 19200
#define OFF_WH  38400
#define OFF_WL  (OFF_WH + WFLOATS)
#define OFF_SPB (OFF_WL + WFLOATS)
#define OFF_W1  (OFF_SPB + BB * HIDP)
#define OFF_ES  (OFF_W1 + HIDP)          // es[2][128]
#define OFF_PS  (OFF_ES + 2 * TILE_L)
#define SMEM_FLOATS (OFF_PS + 8)

__device__ float g_part[BB][NCHUNK][160];
__device__ float g_psum[BB][NCHUNK];
__device__ int   g_done_b[BB];

__device__ __forceinline__ float tanh_approx(float x) {
    float t; asm("tanh.approx.f32 %0, %1;" : "=f"(t) : "f"(x)); return t;
}
__device__ __forceinline__ void cp16(uint32_t saddr, const void* gptr) {
    asm volatile("cp.async.cg.shared.global [%0], [%1], 16;" :: "r"(saddr), "l"(gptr));
}
__device__ __forceinline__ void cp_commit() { asm volatile("cp.async.commit_group;"); }
__device__ __forceinline__ void cp_wait0()  { asm volatile("cp.async.wait_group 0;"); }
__device__ __forceinline__ uint32_t smem_u32(const void* p) {
    uint32_t a;
    asm("{ .reg .u64 t; cvta.to.shared.u64 t, %1; cvt.u32.u64 %0, t; }" : "=r"(a) : "l"(p));
    return a;
}
__device__ __forceinline__ uint32_t bfpack(float2 f) {
    uint32_t r;
    asm("cvt.rn.bf16x2.f32 %0, %1, %2;" : "=r"(r) : "f"(f.y), "f"(f.x));
    return r;
}
__device__ __forceinline__ uint32_t bfres(float2 f, uint32_t h) {
    float hx = __uint_as_float(h << 16);
    float hy = __uint_as_float(h & 0xffff0000u);
    float2 r; r.x = f.x - hx; r.y = f.y - hy;
    return bfpack(r);
}
#define AUX_BAR() asm volatile("bar.sync 1, %0;" :: "n"(NAUX) : "memory")

#define LDSM_X4(r0, r1, r2, r3, addr) \
    asm volatile("ldmatrix.sync.aligned.m8n8.x4.shared.b16 {%0,%1,%2,%3}, [%4];" \
                 : "=r"(r0), "=r"(r1), "=r"(r2), "=r"(r3) : "r"(addr))

#define MMA_BF16(d, a0, a1, a2, a3, b0, b1) \
    asm volatile("mma.sync.aligned.m16n8k16.row.col.f32.bf16.bf16.f32 " \
                 "{%0,%1,%2,%3}, {%4,%5,%6,%7}, {%8,%9}, {%0,%1,%2,%3};" \
                 : "+f"((d)[0]), "+f"((d)[1]), "+f"((d)[2]), "+f"((d)[3]) \
                 : "r"(a0), "r"(a1), "r"(a2), "r"(a3), "r"(b0), "r"(b1))

// ---------------------------------------------------------------------------
// Persistent warp-specialized fused kernel (R14 base).
// R16: MMA issue order is PASS-MAJOR over groups of 5 accumulators so
// consecutive MMAs never share an accumulator (breaks the 6-deep HMMA
// dependency chain that pinned the tensor pipe at ~19%).
// ---------------------------------------------------------------------------
__global__ __launch_bounds__(NTH, 1)
void k_fused(const float* __restrict__ inputs,
             const float* __restrict__ state,
             const int*   __restrict__ cmask,
             const float* __restrict__ W0,
             const float* __restrict__ b0,
             const float* __restrict__ W1,
             const float* __restrict__ b1,
             float* __restrict__ res,
             float* __restrict__ s1_out) {
    extern __shared__ float sm[];
    float* xsbuf[2] = { sm + OFF_XS0, sm + OFF_XS1 };
    float* whf     = sm + OFF_WH;
    float* wlf     = sm + OFF_WL;
    float* spb_all = sm + OFF_SPB;
    float* w1s     = sm + OFF_W1;
    float* esb     = sm + OFF_ES;       // [2][TILE_L]
    float* psred   = sm + OFF_PS;
    __shared__ int s_flag;

    const int tid   = threadIdx.x;
    const int cta   = blockIdx.x;
    const int nw    = (WORKS - cta + GRIDC - 1) / GRIDC;
    const bool is_aux = (tid >= 256);
    const int a_tid = tid - 256;        // 0..127 for aux
    const int lane  = tid & 31;
    const int g     = lane >> 2;
    const int tq    = lane & 3;
    const int R0    = (tid >> 5) << 4;  // GEMM warp's first row

    // --- aux: issue prefetch of tile 0 immediately ---
    if (is_aux) {
        int b = cta >> 5, chunk = cta & 31;
        const char* gb = (const char*)(inputs + ((size_t)b * LL + chunk * TILE_L) * DIN);
        uint32_t sb = smem_u32(xsbuf[0]);
        for (int c = a_tid; c < CHUNK16; c += NAUX) cp16(sb + c * 16, gb + (size_t)c * 16);
        cp_commit();
    }

    // --- stage W hi/lo bf16 (once): zero pads, then fill ---
    for (int idx = tid; idx < 2 * WFLOATS; idx += NTH) whf[idx] = 0.0f;
    __syncthreads();
    for (int idx = tid; idx < 150 * HIDP; idx += NTH) {
        int k = idx / HIDP, j = idx - (idx / HIDP) * HIDP;
        float v = (j < HID) ? W0[(DST + k) * HID + j] : 0.0f;
        __nv_bfloat16 h = __float2bfloat16(v);
        float l = v - __bfloat162float(h);
        ((__nv_bfloat16*)whf)[j * WKS + k] = h;
        ((__nv_bfloat16*)wlf)[j * WKS + k] = __float2bfloat16(l);
    }
    for (int idx = tid; idx < BB * HIDP; idx += NTH) {
        int b = idx / HIDP, j = idx - (idx / HIDP) * HIDP;
        float acc = 0.0f;
        if (j < HID) {
            acc = b0[j];
            const float* st = state + b * DST;
#pragma unroll 15
            for (int k = 0; k < DST; ++k) acc = fmaf(st[k], W0[k * HID + j], acc);
        }
        spb_all[idx] = acc;
    }
    if (tid < HIDP) w1s[tid] = (tid < HID) ? W1[tid] : 0.0f;

    const float b1v = b1[0];
    const uint32_t whb4 = smem_u32(whf) + (lane & 7) * WROWB + (lane >> 3) * 16;
    const uint32_t wlb4 = whb4 + WFLOATS * 4;

    // ---------------- persistent work loop ----------------
    for (int wi = 0; wi < nw; ++wi) {
        const int w     = cta + wi * GRIDC;
        const int b     = w >> 5;
        const int chunk = w & 31;
        const int l0    = chunk * TILE_L;
        const float* xsb = xsbuf[wi & 1];
        float* es = esb + (wi & 1) * TILE_L;

        if (is_aux) cp_wait0();          // tile wi staged
        __syncthreads();                 // tile wi + es[wi-1] visible

        if (!is_aux) {
            // ================= GEMM warps: tile wi =================
            float acc[10][4];
#pragma unroll
            for (int n = 0; n < 10; ++n)
#pragma unroll
                for (int c = 0; c < 4; ++c) acc[n][c] = 0.0f;

            const float* row0 = xsb + (size_t)(R0 + g) * DIN;
            const float* row8 = row0 + 8 * DIN;

#pragma unroll
            for (int sp = 0; sp < 5; ++sp) {
                // ---- A fragments for s = 2*sp (E) and s = 2*sp+1 (O)
                const int kpE = sp * 32 + tq * 2;
                const int kpO = kpE + 16;
                float2 e00 = *(const float2*)(row0 + kpE);
                float2 e10 = *(const float2*)(row8 + kpE);
                float2 e01 = *(const float2*)(row0 + kpE + 8);
                float2 e11 = *(const float2*)(row8 + kpE + 8);
                float2 o00, o10, o01, o11;
                if (sp < 4) {
                    o00 = *(const float2*)(row0 + kpO);
                    o10 = *(const float2*)(row8 + kpO);
                    o01 = *(const float2*)(row0 + kpO + 8);
                    o11 = *(const float2*)(row8 + kpO + 8);
                } else {
                    o01 = make_float2(0.f, 0.f); o11 = o01;
                    if (tq < 3) {
                        o00 = *(const float2*)(row0 + kpO);
                        o10 = *(const float2*)(row8 + kpO);
                    } else { o00 = o01; o10 = o01; }
                }
                uint32_t ahE0 = bfpack(e00), ahE1 = bfpack(e10);
                uint32_t ahE2 = bfpack(e01), ahE3 = bfpack(e11);
                uint32_t alE0 = bfres(e00, ahE0), alE1 = bfres(e10, ahE1);
                uint32_t alE2 = bfres(e01, ahE2), alE3 = bfres(e11, ahE3);
                uint32_t ahO0 = bfpack(o00), ahO1 = bfpack(o10);
                uint32_t ahO2 = bfpack(o01), ahO3 = bfpack(o11);
                uint32_t alO0 = bfres(o00, ahO0), alO1 = bfres(o10, ahO1);
                uint32_t alO2 = bfres(o01, ahO2), alO3 = bfres(o11, ahO3);

                // ---- n in groups of 5; pass-major MMA order (acc spacing 5)
#pragma unroll
                for (int ng = 0; ng < 2; ++ng) {
                    uint32_t bh[5][4], bl[5][4];
#pragma unroll
                    for (int j = 0; j < 5; ++j) {
                        int n = ng * 5 + j;
                        LDSM_X4(bh[j][0], bh[j][1], bh[j][2], bh[j][3],
                                whb4 + n * 2688 + sp * 64);
                        LDSM_X4(bl[j][0], bl[j][1], bl[j][2], bl[j][3],
                                wlb4 + n * 2688 + sp * 64);
                    }
#pragma unroll
                    for (int j = 0; j < 5; ++j)
                        MMA_BF16(acc[ng * 5 + j], ahE0, ahE1, ahE2, ahE3, bh[j][0], bh[j][1]);
#pragma unroll
                    for (int j = 0; j < 5; ++j)
                        MMA_BF16(acc[ng * 5 + j], ahE0, ahE1, ahE2, ahE3, bl[j][0], bl[j][1]);
#pragma unroll
                    for (int j = 0; j < 5; ++j)
                        MMA_BF16(acc[ng * 5 + j], alE0, alE1, alE2, alE3, bh[j][0], bh[j][1]);
#pragma unroll
                    for (int j = 0; j < 5; ++j)
                        MMA_BF16(acc[ng * 5 + j], ahO0, ahO1, ahO2, ahO3, bh[j][2], bh[j][3]);
#pragma unroll
                    for (int j = 0; j < 5; ++j)
                        MMA_BF16(acc[ng * 5 + j], ahO0, ahO1, ahO2, ahO3, bl[j][2], bl[j][3]);
#pragma unroll
                    for (int j = 0; j < 5; ++j)
                        MMA_BF16(acc[ng * 5 + j], alO0, alO1, alO2, alO3, bh[j][2], bh[j][3]);
                }
            }

            // epilogue: tanh + dot(W1), quad reduce, mask + exp
            const float* spb = spb_all + b * HIDP;
            float sA = 0.0f, sB = 0.0f;
#pragma unroll
            for (int n = 0; n < 10; ++n) {
                int c = n * 8 + tq * 2;
                float wv0 = w1s[c], wv1 = w1s[c + 1];
                float p0 = spb[c],  p1 = spb[c + 1];
                sA = fmaf(tanh_approx(acc[n][0] + p0), wv0, sA);
                sA = fmaf(tanh_approx(acc[n][1] + p1), wv1, sA);
                sB = fmaf(tanh_approx(acc[n][2] + p0), wv0, sB);
                sB = fmaf(tanh_approx(acc[n][3] + p1), wv1, sB);
            }
            sA += __shfl_xor_sync(0xffffffffu, sA, 1);
            sA += __shfl_xor_sync(0xffffffffu, sA, 2);
            sB += __shfl_xor_sync(0xffffffffu, sB, 1);
            sB += __shfl_xor_sync(0xffffffffu, sB, 2);
            if (tq == 0) {
                int r = R0 + g;
                size_t idx = (size_t)b * LL + l0 + r;
                float sv = sA + b1v;
                if (cmask[idx] == 0) sv -= 1e30f;
                s1_out[idx] = sv;
                es[r] = __expf(sv);
                int r2 = r + 8;
                size_t idx2 = (size_t)b * LL + l0 + r2;
                float sv2 = sB + b1v;
                if (cmask[idx2] == 0) sv2 -= 1e30f;
                s1_out[idx2] = sv2;
                es[r2] = __expf(sv2);
            }
        } else {
            // ================= aux warps =================
            if (wi > 0) {
                const int wp  = cta + (wi - 1) * GRIDC;
                const int bp  = wp >> 5;
                const int chp = wp & 31;
                const float* xp = xsbuf[(wi - 1) & 1];
                const float* ep = esb + ((wi - 1) & 1) * TILE_L;

                for (int f = a_tid; f < DIN; f += NAUX) {
                    const float* xcol = xp + f;
                    float p0 = 0.f, p1 = 0.f, p2 = 0.f, p3 = 0.f;
#pragma unroll 4
                    for (int r = 0; r < TILE_L; r += 4) {
                        p0 = fmaf(ep[r],     xcol[(size_t)r * DIN],       p0);
                        p1 = fmaf(ep[r + 1], xcol[(size_t)(r + 1) * DIN], p1);
                        p2 = fmaf(ep[r + 2], xcol[(size_t)(r + 2) * DIN], p2);
                        p3 = fmaf(ep[r + 3], xcol[(size_t)(r + 3) * DIN], p3);
                    }
                    g_part[bp][chp][f] = (p0 + p1) + (p2 + p3);
                }
                {
                    float v = ep[a_tid];
                    v += __shfl_xor_sync(0xffffffffu, v, 16);
                    v += __shfl_xor_sync(0xffffffffu, v, 8);
                    v += __shfl_xor_sync(0xffffffffu, v, 4);
                    v += __shfl_xor_sync(0xffffffffu, v, 2);
                    v += __shfl_xor_sync(0xffffffffu, v, 1);
                    if ((a_tid & 31) == 0) psred[a_tid >> 5] = v;
                }
                AUX_BAR();
                if (a_tid == 0) {
                    g_psum[bp][chp] = (psred[0] + psred[1]) + (psred[2] + psred[3]);
                    __threadfence();
                    int old = atomicAdd(&g_done_b[bp], 1);
                    s_flag = (old == NCHUNK - 1);
                }
                AUX_BAR();
                if (s_flag) {
                    __threadfence();
                    for (int f = a_tid; f < DIN; f += NAUX) {
                        float tot = 0.0f;
#pragma unroll
                        for (int c = 0; c < NCHUNK; ++c) tot += g_psum[bp][c];
                        float p = 0.0f;
#pragma unroll
                        for (int c = 0; c < NCHUNK; ++c) p += g_part[bp][c][f];
                        res[bp * DIN + f] = p / tot;
                    }
                    if (a_tid == 0) g_done_b[bp] = 0;
                }
                AUX_BAR();
            }
            if (wi + 1 < nw) {
                int w2 = cta + (wi + 1) * GRIDC;
                int b2 = w2 >> 5, ch2 = w2 & 31;
                const char* gb = (const char*)(inputs + ((size_t)b2 * LL + ch2 * TILE_L) * DIN);
                uint32_t sb = smem_u32(xsbuf[(wi + 1) & 1]);
                for (int c = a_tid; c < CHUNK16; c += NAUX)
                    cp16(sb + c * 16, gb + (size_t)c * 16);
                cp_commit();
            }
        }
    }

    // ---------------- tail: partials/finish for last tile ----------------
    __syncthreads();
    if (is_aux) {
        const int wp  = cta + (nw - 1) * GRIDC;
        const int bp  = wp >> 5;
        const int chp = wp & 31;
        const float* xp = xsbuf[(nw - 1) & 1];
        const float* ep = esb + ((nw - 1) & 1) * TILE_L;
        for (int f = a_tid; f < DIN; f += NAUX) {
            const float* xcol = xp + f;
            float p0 = 0.f, p1 = 0.f, p2 = 0.f, p3 = 0.f;
#pragma unroll 4
            for (int r = 0; r < TILE_L; r += 4) {
                p0 = fmaf(ep[r],     xcol[(size_t)r * DIN],       p0);
                p1 = fmaf(ep[r + 1], xcol[(size_t)(r + 1) * DIN], p1);
                p2 = fmaf(ep[r + 2], xcol[(size_t)(r + 2) * DIN], p2);
                p3 = fmaf(ep[r + 3], xcol[(size_t)(r + 3) * DIN], p3);
            }
            g_part[bp][chp][f] = (p0 + p1) + (p2 + p3);
        }
        {
            float v = ep[a_tid];
            v += __shfl_xor_sync(0xffffffffu, v, 16);
            v += __shfl_xor_sync(0xffffffffu, v, 8);
            v += __shfl_xor_sync(0xffffffffu, v, 4);
            v += __shfl_xor_sync(0xffffffffu, v, 2);
            v += __shfl_xor_sync(0xffffffffu, v, 1);
            if ((a_tid & 31) == 0) psred[a_tid >> 5] = v;
        }
        AUX_BAR();
        if (a_tid == 0) {
            g_psum[bp][chp] = (psred[0] + psred[1]) + (psred[2] + psred[3]);
            __threadfence();
            int old = atomicAdd(&g_done_b[bp], 1);
            s_flag = (old == NCHUNK - 1);
        }
        AUX_BAR();
        if (s_flag) {
            __threadfence();
            for (int f = a_tid; f < DIN; f += NAUX) {
                float tot = 0.0f;
#pragma unroll
                for (int c = 0; c < NCHUNK; ++c) tot += g_psum[bp][c];
                float p = 0.0f;
#pragma unroll
                for (int c = 0; c < NCHUNK; ++c) p += g_part[bp][c][f];
                res[bp * DIN + f] = p / tot;
            }
            if (a_tid == 0) g_done_b[bp] = 0;
        }
    }
}

// ---------------------------------------------------------------------------
extern "C" void kernel_launch(void* const* d_in, const int* in_sizes, int n_in,
                              void* d_out, int out_size) {
    const float* inputs = (const float*)d_in[0];
    const float* state  = (const float*)d_in[1];
    const int*   cmask  = (const int*)d_in[2];   // bool transported as int32
    const float* W0     = (const float*)d_in[3];
    const float* b0     = (const float*)d_in[4];
    const float* W1     = (const float*)d_in[5];
    const float* b1     = (const float*)d_in[6];

    float* out = (float*)d_out;
    float* res = out;                 // [B][1][DIN]
    float* s1  = out + BB * DIN;      // [B][L]

    const int smem = SMEM_FLOATS * (int)sizeof(float);
    cudaFuncSetAttribute(k_fused, cudaFuncAttributeMaxDynamicSharedMemorySize, smem);
    k_fused<<<GRIDC, NTH, smem>>>(inputs, state, cmask, W0, b0, W1, b1, res, s1);
}